// round 12
// baseline (speedup 1.0000x reference)
#include <cuda_runtime.h>
#include <cuda_bf16.h>
#include <cstdint>

#define NPOS 4096
#define NROWS 8192
#define EXP_OFF 40.0f

// ---- scratch (device globals; allocation-free rule) ----
__device__ __align__(16) __nv_bfloat16 g_wth[192 * 256], g_wtl[192 * 256];   // [3*64 n][256 k]
__device__ __align__(16) __nv_bfloat16 g_woth[256 * 64], g_wotl[256 * 64];   // [256 n][64 k]
__device__ __align__(16) __nv_bfloat16 g_kh[NROWS * 64], g_kl[NROWS * 64];   // flash-Q role
__device__ __align__(16) __nv_bfloat16 g_qh[NROWS * 64], g_ql[NROWS * 64];   // flash-K role
__device__ __align__(16) __nv_bfloat16 g_vh[NROWS * 64], g_vl[NROWS * 64];   // V
__device__ __align__(16) float g_opart[4 * NROWS * 64];  // [split][row][d]
__device__ __align__(16) float g_lpart[4 * NROWS];       // [split][row]

__device__ __forceinline__ uint32_t smem_to_u32(const void* p) {
    uint32_t a;
    asm("{ .reg .u64 t; cvta.to.shared.u64 t, %1; cvt.u32.u64 %0, t; }" : "=r"(a) : "l"(p));
    return a;
}
#define CP_ASYNC16(dst, src) asm volatile( \
    "cp.async.cg.shared.global [%0], [%1], 16;" :: "r"(dst), "l"(src) : "memory")
#define CP_COMMIT() asm volatile("cp.async.commit_group;" ::: "memory")
#define CP_WAIT(N)  asm volatile("cp.async.wait_group %0;" :: "n"(N) : "memory")

#define LDSM_X4(r, a) asm volatile( \
    "ldmatrix.sync.aligned.m8n8.x4.shared.b16 {%0,%1,%2,%3}, [%4];" \
    : "=r"((r)[0]), "=r"((r)[1]), "=r"((r)[2]), "=r"((r)[3]) : "r"(a))
#define LDSM_X4T(r, a) asm volatile( \
    "ldmatrix.sync.aligned.m8n8.x4.trans.shared.b16 {%0,%1,%2,%3}, [%4];" \
    : "=r"((r)[0]), "=r"((r)[1]), "=r"((r)[2]), "=r"((r)[3]) : "r"(a))
#define MMA_BF16(c, a, b0, b1) asm volatile( \
    "mma.sync.aligned.m16n8k16.row.col.f32.bf16.bf16.f32 " \
    "{%0,%1,%2,%3}, {%4,%5,%6,%7}, {%8,%9}, {%0,%1,%2,%3};" \
    : "+f"((c)[0]), "+f"((c)[1]), "+f"((c)[2]), "+f"((c)[3]) \
    : "r"((a)[0]), "r"((a)[1]), "r"((a)[2]), "r"((a)[3]), "r"(b0), "r"(b1))

__device__ __forceinline__ void split2pack(float a, float b, uint32_t& hi, uint32_t& lo) {
    __nv_bfloat16 h0 = __float2bfloat16(a), h1 = __float2bfloat16(b);
    __nv_bfloat162 hh = __halves2bfloat162(h0, h1);
    __nv_bfloat162 ll = __floats2bfloat162_rn(a - __bfloat162float(h0),
                                              b - __bfloat162float(h1));
    hi = *(uint32_t*)&hh; lo = *(uint32_t*)&ll;
}

// ============ Kernel 0: transpose+split W (192x256) and Wo (256x64) ============
__global__ __launch_bounds__(256) void split_w_kernel(
    const float* __restrict__ Wk, const float* __restrict__ Wq,
    const float* __restrict__ Wv, const float* __restrict__ Wo)
{
    const int bid = blockIdx.x, tid = threadIdx.x;
    if (bid < 192) {                               // Wk/Wq/Wv: 49152 elems
        int j = bid * 256 + tid;
        int m = j >> 14, rem = j & 16383;
        int k = rem >> 6, n = rem & 63;
        const float* W = (m == 0) ? Wk : (m == 1) ? Wq : Wv;
        float v = W[k * 64 + n];
        __nv_bfloat16 h = __float2bfloat16(v);
        int di = (m * 64 + n) * 256 + k;
        g_wth[di] = h;
        g_wtl[di] = __float2bfloat16(v - __bfloat162float(h));
    } else {                                        // Wo: 16384 elems
        int j = (bid - 192) * 256 + tid;
        int k = j >> 8, n = j & 255;
        float v = Wo[k * 256 + n];
        __nv_bfloat16 h = __float2bfloat16(v);
        g_woth[n * 64 + k] = h;
        g_wotl[n * 64 + k] = __float2bfloat16(v - __bfloat162float(h));
    }
}

// ============ Kernel 1: fused x-split + proj mma: [8192,256]@[256,192] ============
// Grid 256 x 32 rows; 8 warps (2 rowgrp x 4 colgrp of 6 n8-tiles).
// Buffer: [0,4096) A fp32 stage 32x32 pitch128; [4096,+2560) Ah; +2560 Al;
//         then Bh (192x32 pitch80 =15360), Bl.
#define PSTG 4096
#define PASZ 2560
#define PBSZ 15360
#define PBUF 39936

__device__ __forceinline__ void proj_load(uint32_t sb, int buf, int row0, int k0, int tid,
                                          const float* __restrict__ x) {
    {   // A: fp32 tile 32x32 (256 chunks)
        int r = tid >> 3, c4 = tid & 7;
        const char* g = (const char*)(x + (size_t)(row0 + r) * 256 + k0 + c4 * 4);
        CP_ASYNC16(sb + buf * PBUF + r * 128 + c4 * 16, g);
    }
#pragma unroll
    for (int i = 0; i < 6; i++) {                   // B: 1536 chunks
        int j = tid + i * 256;
        int hl = j >= 768; int jj = j - (hl ? 768 : 0);
        int r = jj >> 2, c = jj & 3;
        const __nv_bfloat16* src = (hl ? g_wtl : g_wth) + (size_t)r * 256 + k0 + c * 8;
        CP_ASYNC16(sb + buf * PBUF + PSTG + 2 * PASZ + hl * PBSZ + r * 80 + c * 16,
                   (const char*)src);
    }
}

__global__ __launch_bounds__(256, 1) void proj_mma(const float* __restrict__ x)
{
    extern __shared__ __align__(16) char smem[];
    const uint32_t sb = smem_to_u32(smem);
    const int tid = threadIdx.x;
    const int wid = tid >> 5, lane = tid & 31;
    const int rg = wid & 1, cg = wid >> 1;
    const int row0 = blockIdx.x * 32;

    float c[6][4];
#pragma unroll
    for (int t = 0; t < 6; t++)
#pragma unroll
        for (int j = 0; j < 4; j++) c[t][j] = 0.f;

    proj_load(sb, 0, row0, 0, tid, x);
    CP_COMMIT();

    for (int ch = 0; ch < 8; ch++) {
        __syncthreads();
        if (ch + 1 < 8) {
            proj_load(sb, (ch + 1) & 1, row0, (ch + 1) * 32, tid, x);
            CP_COMMIT(); CP_WAIT(1);
        } else CP_WAIT(0);
        __syncthreads();

        const uint32_t base = sb + (ch & 1) * PBUF;
        {   // convert A fp32 -> bf16 hi/lo (4 floats per thread)
            int r = tid >> 3, cc = (tid & 7) * 4;
            float4 v = *(const float4*)(smem + (ch & 1) * PBUF + r * 128 + cc * 4);
            uint32_t h0, l0, h1, l1;
            split2pack(v.x, v.y, h0, l0);
            split2pack(v.z, v.w, h1, l1);
            *(uint2*)(smem + (ch & 1) * PBUF + PSTG + r * 80 + cc * 2) = make_uint2(h0, h1);
            *(uint2*)(smem + (ch & 1) * PBUF + PSTG + PASZ + r * 80 + cc * 2) = make_uint2(l0, l1);
        }
        __syncthreads();

        uint32_t ah[2][4], al[2][4];
#pragma unroll
        for (int kt = 0; kt < 2; kt++) {
            uint32_t a = base + PSTG + (16 * rg + (lane & 15)) * 80 + kt * 32 + ((lane >> 4) << 4);
            LDSM_X4(ah[kt], a);
            LDSM_X4(al[kt], a + PASZ);
        }
#pragma unroll
        for (int t = 0; t < 6; t++) {
            int g = cg * 6 + t;
            uint32_t bh[4], bl[4];
            uint32_t ba = base + PSTG + 2 * PASZ + (8 * g + (lane & 7)) * 80 + ((lane >> 3) & 3) * 16;
            LDSM_X4(bh, ba);
            LDSM_X4(bl, ba + PBSZ);
            MMA_BF16(c[t], ah[0], bh[0], bh[1]);
            MMA_BF16(c[t], al[0], bh[0], bh[1]);
            MMA_BF16(c[t], ah[0], bl[0], bl[1]);
            MMA_BF16(c[t], ah[1], bh[2], bh[3]);
            MMA_BF16(c[t], al[1], bh[2], bh[3]);
            MMA_BF16(c[t], ah[1], bl[2], bl[3]);
        }
    }

    uint32_t* hip[3] = { (uint32_t*)g_kh, (uint32_t*)g_qh, (uint32_t*)g_vh };
    uint32_t* lop[3] = { (uint32_t*)g_kl, (uint32_t*)g_ql, (uint32_t*)g_vl };
    const int r1 = row0 + 16 * rg + (lane >> 2);
#pragma unroll
    for (int t = 0; t < 6; t++) {
        int g = cg * 6 + t;
        int mat = g >> 3, cu = (g & 7) * 4 + (lane & 3);
        uint32_t h0, l0, h1, l1;
        split2pack(c[t][0], c[t][1], h0, l0);
        split2pack(c[t][2], c[t][3], h1, l1);
        hip[mat][(size_t)r1 * 32 + cu] = h0;
        lop[mat][(size_t)r1 * 32 + cu] = l0;
        hip[mat][(size_t)(r1 + 8) * 32 + cu] = h1;
        lop[mat][(size_t)(r1 + 8) * 32 + cu] = l1;
    }
}

// =================== Kernel 2: mma.sync flash attention ===================
// Grid 256 = [split4][batch2][qblock32]; 16 KV tiles per CTA; 2 CTAs/SM.
#define ROWB 144
#define MATB 9216
#define BUFB 36864

__device__ __forceinline__ void load_tile(uint32_t sb, int buf, int grow0, int tid) {
    const __nv_bfloat16* srcs[4] = { g_qh, g_ql, g_vh, g_vl };
#pragma unroll
    for (int i = 0; i < 8; i++) {
        int idx = tid + i * 256;
        int mat = idx >> 9;
        int r = (idx >> 3) & 63, c8 = idx & 7;
        const char* g = (const char*)(srcs[mat] + (size_t)(grow0 + r) * 64 + c8 * 8);
        uint32_t d = sb + buf * BUFB + mat * MATB + r * ROWB + c8 * 16;
        CP_ASYNC16(d, g);
    }
}

__global__ __launch_bounds__(256, 2) void attn_kernel()
{
    extern __shared__ __align__(16) char smem[];
    const uint32_t sb = smem_to_u32(smem);
    const int tid = threadIdx.x;
    const int wid = tid >> 5, lane = tid & 31;
    const int split = blockIdx.x >> 6;
    const int b = (blockIdx.x >> 5) & 1;
    const int n0 = (blockIdx.x & 31) * 128;
    const int kv0 = b * NPOS + split * 1024;
    const int r0 = wid << 4;

    // stage Q (hi at 0, lo at 18432), then ldmatrix into registers
#pragma unroll
    for (int i = 0; i < 8; i++) {
        int idx = tid + i * 256;
        int m = idx >> 10;
        int r = (idx >> 3) & 127, c8 = idx & 7;
        const __nv_bfloat16* src = m ? g_kl : g_kh;
        const char* g = (const char*)(src + (size_t)(b * NPOS + n0 + r) * 64 + c8 * 8);
        CP_ASYNC16(sb + m * 18432 + r * ROWB + c8 * 16, g);
    }
    CP_COMMIT(); CP_WAIT(0);
    __syncthreads();

    uint32_t qh[4][4], ql[4][4];
#pragma unroll
    for (int kt = 0; kt < 4; kt++) {
        uint32_t a = sb + (r0 + (lane & 15)) * ROWB + (16 * kt + ((lane >> 4) << 3)) * 2;
        LDSM_X4(qh[kt], a);
        LDSM_X4(ql[kt], a + 18432);
    }
    __syncthreads();

    float o[8][4];
#pragma unroll
    for (int i = 0; i < 8; i++)
#pragma unroll
        for (int j = 0; j < 4; j++) o[i][j] = 0.f;
    float lsum0 = 0.f, lsum1 = 0.f;

    load_tile(sb, 0, kv0, tid);
    CP_COMMIT();

    for (int t = 0; t < 16; t++) {
        __syncthreads();
        if (t + 1 < 16) {
            load_tile(sb, (t + 1) & 1, kv0 + (t + 1) * 64, tid);
            CP_COMMIT(); CP_WAIT(1);
        } else CP_WAIT(0);
        __syncthreads();

        const uint32_t base = sb + (t & 1) * BUFB;

#pragma unroll
        for (int j = 0; j < 4; j++) {
            uint32_t ph[4], pl[4];
            // S for column group j (2 nt halves), then exp & pack
#pragma unroll
            for (int h = 0; h < 2; h++) {
                int nt = 2 * j + h;
                float c[4] = {0.f, 0.f, 0.f, 0.f};
                uint32_t arow = base + (8 * nt + (lane & 7)) * ROWB + ((lane >> 3) & 3) * 16;
#pragma unroll
                for (int kp = 0; kp < 2; kp++) {
                    uint32_t bh[4], bl[4];
                    LDSM_X4(bh, arow + kp * 64);
                    LDSM_X4(bl, arow + kp * 64 + MATB);
                    MMA_BF16(c, qh[2 * kp], bh[0], bh[1]);
                    MMA_BF16(c, ql[2 * kp], bh[0], bh[1]);
                    MMA_BF16(c, qh[2 * kp], bl[0], bl[1]);
                    MMA_BF16(c, qh[2 * kp + 1], bh[2], bh[3]);
                    MMA_BF16(c, ql[2 * kp + 1], bh[2], bh[3]);
                    MMA_BF16(c, qh[2 * kp + 1], bl[2], bl[3]);
                }
                float p0 = __expf(c[0] - EXP_OFF), p1 = __expf(c[1] - EXP_OFF);
                float p2 = __expf(c[2] - EXP_OFF), p3 = __expf(c[3] - EXP_OFF);
                lsum0 += p0 + p1; lsum1 += p2 + p3;
                split2pack(p0, p1, ph[2 * h], pl[2 * h]);
                split2pack(p2, p3, ph[2 * h + 1], pl[2 * h + 1]);
            }
            // PV for column group j
#pragma unroll
            for (int dp = 0; dp < 4; dp++) {
                uint32_t av = base + 2 * MATB + (16 * j + (lane & 15)) * ROWB
                              + dp * 32 + ((lane >> 4) & 1) * 16;
                uint32_t vh[4], vl[4];
                LDSM_X4T(vh, av);
                LDSM_X4T(vl, av + MATB);
                MMA_BF16(o[2 * dp], ph, vh[0], vh[1]);
                MMA_BF16(o[2 * dp], pl, vh[0], vh[1]);
                MMA_BF16(o[2 * dp], ph, vl[0], vl[1]);
                MMA_BF16(o[2 * dp + 1], ph, vh[2], vh[3]);
                MMA_BF16(o[2 * dp + 1], pl, vh[2], vh[3]);
                MMA_BF16(o[2 * dp + 1], ph, vl[2], vl[3]);
            }
        }
    }

    lsum0 += __shfl_xor_sync(0xffffffffu, lsum0, 1);
    lsum0 += __shfl_xor_sync(0xffffffffu, lsum0, 2);
    lsum1 += __shfl_xor_sync(0xffffffffu, lsum1, 1);
    lsum1 += __shfl_xor_sync(0xffffffffu, lsum1, 2);

    const int rg = b * NPOS + n0 + r0 + (lane >> 2);
    float* dst = g_opart + (size_t)split * NROWS * 64;
#pragma unroll
    for (int dt = 0; dt < 8; dt++) {
        ((float2*)(dst + (size_t)rg * 64 + dt * 8))[lane & 3] =
            make_float2(o[dt][0], o[dt][1]);
        ((float2*)(dst + (size_t)(rg + 8) * 64 + dt * 8))[lane & 3] =
            make_float2(o[dt][2], o[dt][3]);
    }
    if ((lane & 3) == 0) {
        g_lpart[split * NROWS + rg] = lsum0;
        g_lpart[split * NROWS + rg + 8] = lsum1;
    }
}

// ====== Kernel 3: combine 4 splits + outproj via mma + BN epilogue ======
// Grid 256 x 32 rows; 8 warps = 2 rowgrp(m16) x 4 colgrp(64 cols = 8 n8).
#define OASZ 4608
#define OBSZ 36864

__global__ __launch_bounds__(256, 1) void outproj_mma(
    const float* __restrict__ gamma, const float* __restrict__ beta,
    float* __restrict__ out)
{
    extern __shared__ __align__(16) char smem[];
    const uint32_t sb = smem_to_u32(smem);
    const int tid = threadIdx.x;
    const int wid = tid >> 5, lane = tid & 31;
    const int rg = wid & 1, cg = wid >> 1;
    const int row0 = blockIdx.x * 32;

    // stage B (Wo^T split) via cp.async
#pragma unroll
    for (int i = 0; i < 16; i++) {
        int idx = tid + i * 256;
        int hl = idx >> 11, jj = idx & 2047;
        int r = jj >> 3, c = jj & 7;
        const __nv_bfloat16* src = (hl ? g_wotl : g_woth) + (size_t)r * 64 + c * 8;
        CP_ASYNC16(sb + 2 * OASZ + hl * OBSZ + r * ROWB + c * 16, (const char*)src);
    }
    CP_COMMIT();

    // stage A: combine 4 split-KV partials, normalize, split to bf16
    {
        int r = tid >> 3, cq = tid & 7;
        int rgr = row0 + r;
        float inv = 1.f / (g_lpart[rgr] + g_lpart[NROWS + rgr]
                         + g_lpart[2 * NROWS + rgr] + g_lpart[3 * NROWS + rgr]);
#pragma unroll
        for (int e = 0; e < 2; e++) {
            int c4 = cq * 2 + e;
            float4 u = ((const float4*)(g_opart + (size_t)rgr * 64))[c4];
#pragma unroll
            for (int s = 1; s < 4; s++) {
                float4 w = ((const float4*)(g_opart + (size_t)s * NROWS * 64
                                            + (size_t)rgr * 64))[c4];
                u.x += w.x; u.y += w.y; u.z += w.z; u.w += w.w;
            }
            u.x *= inv; u.y *= inv; u.z *= inv; u.w *= inv;
            uint32_t h0, l0, h1, l1;
            split2pack(u.x, u.y, h0, l0);
            split2pack(u.z, u.w, h1, l1);
            *(uint2*)(smem + r * ROWB + c4 * 8) = make_uint2(h0, h1);
            *(uint2*)(smem + OASZ + r * ROWB + c4 * 8) = make_uint2(l0, l1);
        }
    }
    CP_WAIT(0);
    __syncthreads();

    uint32_t ah[4][4], al[4][4];
#pragma unroll
    for (int kt = 0; kt < 4; kt++) {
        uint32_t a = sb + (16 * rg + (lane & 15)) * ROWB + kt * 32 + ((lane >> 4) << 4);
        LDSM_X4(ah[kt], a);
        LDSM_X4(al[kt], a + OASZ);
    }

    float acc[8][4];
#pragma unroll
    for (int t = 0; t < 8; t++)
#pragma unroll
        for (int j = 0; j < 4; j++) acc[t][j] = 0.f;

#pragma unroll
    for (int t = 0; t < 8; t++) {
        int nrow0 = cg * 64 + t * 8;
#pragma unroll
        for (int kp = 0; kp < 2; kp++) {
            uint32_t bh[4], bl[4];
            uint32_t ba = sb + 2 * OASZ + (nrow0 + (lane & 7)) * ROWB
                          + kp * 64 + ((lane >> 3) & 3) * 16;
            LDSM_X4(bh, ba);
            LDSM_X4(bl, ba + OBSZ);
            MMA_BF16(acc[t], ah[2 * kp], bh[0], bh[1]);
            MMA_BF16(acc[t], al[2 * kp], bh[0], bh[1]);
            MMA_BF16(acc[t], ah[2 * kp], bl[0], bl[1]);
            MMA_BF16(acc[t], ah[2 * kp + 1], bh[2], bh[3]);
            MMA_BF16(acc[t], al[2 * kp + 1], bh[2], bh[3]);
            MMA_BF16(acc[t], ah[2 * kp + 1], bl[2], bl[3]);
        }
    }

    const float sc = rsqrtf(1.0f + 1e-3f);
    const int r1 = row0 + 16 * rg + (lane >> 2);
#pragma unroll
    for (int t = 0; t < 8; t++) {
        int col = cg * 64 + t * 8 + (lane & 3) * 2;
        float g0 = __ldg(gamma + col) * sc, g1 = __ldg(gamma + col + 1) * sc;
        float b0 = __ldg(beta + col), b1 = __ldg(beta + col + 1);
        *(float2*)(out + (size_t)r1 * 256 + col) =
            make_float2(fmaf(acc[t][0], g0, b0), fmaf(acc[t][1], g1, b1));
        *(float2*)(out + (size_t)(r1 + 8) * 256 + col) =
            make_float2(fmaf(acc[t][2], g0, b0), fmaf(acc[t][3], g1, b1));
    }
}

extern "C" void kernel_launch(void* const* d_in, const int* in_sizes, int n_in,
                              void* d_out, int out_size) {
    const float* x     = (const float*)d_in[0];
    const float* Wk    = (const float*)d_in[1];
    const float* Wq    = (const float*)d_in[2];
    const float* Wv    = (const float*)d_in[3];
    const float* Wo    = (const float*)d_in[4];
    const float* gamma = (const float*)d_in[5];
    const float* beta  = (const float*)d_in[6];
    float* out = (float*)d_out;

    cudaFuncSetAttribute(proj_mma, cudaFuncAttributeMaxDynamicSharedMemorySize, 2 * PBUF);
    cudaFuncSetAttribute(attn_kernel, cudaFuncAttributeMaxDynamicSharedMemorySize, 2 * BUFB);
    cudaFuncSetAttribute(outproj_mma, cudaFuncAttributeMaxDynamicSharedMemorySize,
                         2 * OASZ + 2 * OBSZ);

    split_w_kernel<<<256, 256>>>(Wk, Wq, Wv, Wo);
    proj_mma<<<256, 256, 2 * PBUF>>>(x);
    attn_kernel<<<256, 256, 2 * BUFB>>>();
    outproj_mma<<<256, 256, 2 * OASZ + 2 * OBSZ>>>(gamma, beta, out);
}

// round 13
// speedup vs baseline: 1.0539x; 1.0539x over previous
#include <cuda_runtime.h>
#include <cuda_bf16.h>
#include <cuda_fp16.h>
#include <cstdint>

#define NPOS 4096
#define NROWS 8192

// ---- scratch (device globals; allocation-free rule) ----
__device__ __align__(16) __nv_bfloat16 g_wth[192 * 256], g_wtl[192 * 256];   // [3*64 n][256 k]
__device__ __align__(16) __nv_bfloat16 g_woth[256 * 64], g_wotl[256 * 64];   // [256 n][64 k]
__device__ __align__(16) __nv_bfloat16 g_kh[NROWS * 64], g_kl[NROWS * 64];   // flash-Q role (bf16)
__device__ __align__(16) __nv_bfloat16 g_qh[NROWS * 64], g_ql[NROWS * 64];   // flash-K role (bf16)
__device__ __align__(16) __half        g_vh[NROWS * 64], g_vl[NROWS * 64];   // V (fp16 split)
__device__ __align__(16) float g_opart[4 * NROWS * 64];  // [split][row][d]
__device__ __align__(16) float g_lpart[4 * NROWS];       // [split][row]
__device__ __align__(16) float g_mpart[4 * NROWS];       // [split][row]

__device__ __forceinline__ uint32_t smem_to_u32(const void* p) {
    uint32_t a;
    asm("{ .reg .u64 t; cvta.to.shared.u64 t, %1; cvt.u32.u64 %0, t; }" : "=r"(a) : "l"(p));
    return a;
}
#define CP_ASYNC16(dst, src) asm volatile( \
    "cp.async.cg.shared.global [%0], [%1], 16;" :: "r"(dst), "l"(src) : "memory")
#define CP_COMMIT() asm volatile("cp.async.commit_group;" ::: "memory")
#define CP_WAIT(N)  asm volatile("cp.async.wait_group %0;" :: "n"(N) : "memory")

#define LDSM_X4(r, a) asm volatile( \
    "ldmatrix.sync.aligned.m8n8.x4.shared.b16 {%0,%1,%2,%3}, [%4];" \
    : "=r"((r)[0]), "=r"((r)[1]), "=r"((r)[2]), "=r"((r)[3]) : "r"(a))
#define LDSM_X4T(r, a) asm volatile( \
    "ldmatrix.sync.aligned.m8n8.x4.trans.shared.b16 {%0,%1,%2,%3}, [%4];" \
    : "=r"((r)[0]), "=r"((r)[1]), "=r"((r)[2]), "=r"((r)[3]) : "r"(a))
#define MMA_BF16(c, a, b0, b1) asm volatile( \
    "mma.sync.aligned.m16n8k16.row.col.f32.bf16.bf16.f32 " \
    "{%0,%1,%2,%3}, {%4,%5,%6,%7}, {%8,%9}, {%0,%1,%2,%3};" \
    : "+f"((c)[0]), "+f"((c)[1]), "+f"((c)[2]), "+f"((c)[3]) \
    : "r"((a)[0]), "r"((a)[1]), "r"((a)[2]), "r"((a)[3]), "r"(b0), "r"(b1))
#define MMA_FP16(c, a, b0, b1) asm volatile( \
    "mma.sync.aligned.m16n8k16.row.col.f32.f16.f16.f32 " \
    "{%0,%1,%2,%3}, {%4,%5,%6,%7}, {%8,%9}, {%0,%1,%2,%3};" \
    : "+f"((c)[0]), "+f"((c)[1]), "+f"((c)[2]), "+f"((c)[3]) \
    : "r"((a)[0]), "r"((a)[1]), "r"((a)[2]), "r"((a)[3]), "r"(b0), "r"(b1))

__device__ __forceinline__ void split2pack(float a, float b, uint32_t& hi, uint32_t& lo) {
    __nv_bfloat16 h0 = __float2bfloat16(a), h1 = __float2bfloat16(b);
    __nv_bfloat162 hh = __halves2bfloat162(h0, h1);
    __nv_bfloat162 ll = __floats2bfloat162_rn(a - __bfloat162float(h0),
                                              b - __bfloat162float(h1));
    hi = *(uint32_t*)&hh; lo = *(uint32_t*)&ll;
}
__device__ __forceinline__ void split2pack_h(float a, float b, uint32_t& hi, uint32_t& lo) {
    __half h0 = __float2half_rn(a), h1 = __float2half_rn(b);
    __half2 hh = __halves2half2(h0, h1);
    __half2 ll = __floats2half2_rn(a - __half2float(h0), b - __half2float(h1));
    hi = *(uint32_t*)&hh; lo = *(uint32_t*)&ll;
}
__device__ __forceinline__ uint32_t pack_h2(float a, float b) {
    __half2 h = __floats2half2_rn(a, b);
    return *(uint32_t*)&h;
}

// ============ Kernel 0: transpose+split W (192x256) and Wo (256x64) ============
__global__ __launch_bounds__(256) void split_w_kernel(
    const float* __restrict__ Wk, const float* __restrict__ Wq,
    const float* __restrict__ Wv, const float* __restrict__ Wo)
{
    const int bid = blockIdx.x, tid = threadIdx.x;
    if (bid < 192) {
        int j = bid * 256 + tid;
        int m = j >> 14, rem = j & 16383;
        int k = rem >> 6, n = rem & 63;
        const float* W = (m == 0) ? Wk : (m == 1) ? Wq : Wv;
        float v = W[k * 64 + n];
        __nv_bfloat16 h = __float2bfloat16(v);
        int di = (m * 64 + n) * 256 + k;
        g_wth[di] = h;
        g_wtl[di] = __float2bfloat16(v - __bfloat162float(h));
    } else {
        int j = (bid - 192) * 256 + tid;
        int k = j >> 8, n = j & 255;
        float v = Wo[k * 256 + n];
        __nv_bfloat16 h = __float2bfloat16(v);
        g_woth[n * 64 + k] = h;
        g_wotl[n * 64 + k] = __float2bfloat16(v - __bfloat162float(h));
    }
}

// ============ Kernel 1: fused x-split + proj mma: [8192,256]@[256,192] ============
#define PSTG 4096
#define PASZ 2560
#define PBSZ 15360
#define PBUF 39936

__device__ __forceinline__ void proj_load(uint32_t sb, int buf, int row0, int k0, int tid,
                                          const float* __restrict__ x) {
    {
        int r = tid >> 3, c4 = tid & 7;
        const char* g = (const char*)(x + (size_t)(row0 + r) * 256 + k0 + c4 * 4);
        CP_ASYNC16(sb + buf * PBUF + r * 128 + c4 * 16, g);
    }
#pragma unroll
    for (int i = 0; i < 6; i++) {
        int j = tid + i * 256;
        int hl = j >= 768; int jj = j - (hl ? 768 : 0);
        int r = jj >> 2, c = jj & 3;
        const __nv_bfloat16* src = (hl ? g_wtl : g_wth) + (size_t)r * 256 + k0 + c * 8;
        CP_ASYNC16(sb + buf * PBUF + PSTG + 2 * PASZ + hl * PBSZ + r * 80 + c * 16,
                   (const char*)src);
    }
}

__global__ __launch_bounds__(256, 1) void proj_mma(const float* __restrict__ x)
{
    extern __shared__ __align__(16) char smem[];
    const uint32_t sb = smem_to_u32(smem);
    const int tid = threadIdx.x;
    const int wid = tid >> 5, lane = tid & 31;
    const int rg = wid & 1, cg = wid >> 1;
    const int row0 = blockIdx.x * 32;

    float c[6][4];
#pragma unroll
    for (int t = 0; t < 6; t++)
#pragma unroll
        for (int j = 0; j < 4; j++) c[t][j] = 0.f;

    proj_load(sb, 0, row0, 0, tid, x);
    CP_COMMIT();

    for (int ch = 0; ch < 8; ch++) {
        __syncthreads();
        if (ch + 1 < 8) {
            proj_load(sb, (ch + 1) & 1, row0, (ch + 1) * 32, tid, x);
            CP_COMMIT(); CP_WAIT(1);
        } else CP_WAIT(0);
        __syncthreads();

        const uint32_t base = sb + (ch & 1) * PBUF;
        {
            int r = tid >> 3, cc = (tid & 7) * 4;
            float4 v = *(const float4*)(smem + (ch & 1) * PBUF + r * 128 + cc * 4);
            uint32_t h0, l0, h1, l1;
            split2pack(v.x, v.y, h0, l0);
            split2pack(v.z, v.w, h1, l1);
            *(uint2*)(smem + (ch & 1) * PBUF + PSTG + r * 80 + cc * 2) = make_uint2(h0, h1);
            *(uint2*)(smem + (ch & 1) * PBUF + PSTG + PASZ + r * 80 + cc * 2) = make_uint2(l0, l1);
        }
        __syncthreads();

        uint32_t ah[2][4], al[2][4];
#pragma unroll
        for (int kt = 0; kt < 2; kt++) {
            uint32_t a = base + PSTG + (16 * rg + (lane & 15)) * 80 + kt * 32 + ((lane >> 4) << 4);
            LDSM_X4(ah[kt], a);
            LDSM_X4(al[kt], a + PASZ);
        }
#pragma unroll
        for (int t = 0; t < 6; t++) {
            int g = cg * 6 + t;
            uint32_t bh[4], bl[4];
            uint32_t ba = base + PSTG + 2 * PASZ + (8 * g + (lane & 7)) * 80 + ((lane >> 3) & 3) * 16;
            LDSM_X4(bh, ba);
            LDSM_X4(bl, ba + PBSZ);
            MMA_BF16(c[t], ah[0], bh[0], bh[1]);
            MMA_BF16(c[t], al[0], bh[0], bh[1]);
            MMA_BF16(c[t], ah[0], bl[0], bl[1]);
            MMA_BF16(c[t], ah[1], bh[2], bh[3]);
            MMA_BF16(c[t], al[1], bh[2], bh[3]);
            MMA_BF16(c[t], ah[1], bl[2], bl[3]);
        }
    }

    uint32_t* hip[3] = { (uint32_t*)g_kh, (uint32_t*)g_qh, (uint32_t*)g_vh };
    uint32_t* lop[3] = { (uint32_t*)g_kl, (uint32_t*)g_ql, (uint32_t*)g_vl };
    const int r1 = row0 + 16 * rg + (lane >> 2);
#pragma unroll
    for (int t = 0; t < 6; t++) {
        int g = cg * 6 + t;
        int mat = g >> 3, cu = (g & 7) * 4 + (lane & 3);
        uint32_t h0, l0, h1, l1;
        if (mat == 2) {
            split2pack_h(c[t][0], c[t][1], h0, l0);
            split2pack_h(c[t][2], c[t][3], h1, l1);
        } else {
            split2pack(c[t][0], c[t][1], h0, l0);
            split2pack(c[t][2], c[t][3], h1, l1);
        }
        hip[mat][(size_t)r1 * 32 + cu] = h0;
        lop[mat][(size_t)r1 * 32 + cu] = l0;
        hip[mat][(size_t)(r1 + 8) * 32 + cu] = h1;
        lop[mat][(size_t)(r1 + 8) * 32 + cu] = l1;
    }
}

// =================== Kernel 2: mma.sync flash attention (online max) ===================
// Grid 256 = [split4][batch2][qblock32]; 16 KV tiles per CTA; 2 CTAs/SM.
#define ROWB 144
#define MATB 9216
#define BUFB 36864

__device__ __forceinline__ void load_tile(uint32_t sb, int buf, int grow0, int tid) {
    const char* srcs[4] = { (const char*)g_qh, (const char*)g_ql,
                            (const char*)g_vh, (const char*)g_vl };
#pragma unroll
    for (int i = 0; i < 8; i++) {
        int idx = tid + i * 256;
        int mat = idx >> 9;
        int r = (idx >> 3) & 63, c8 = idx & 7;
        const char* g = srcs[mat] + ((size_t)(grow0 + r) * 64 + c8 * 8) * 2;
        uint32_t d = sb + buf * BUFB + mat * MATB + r * ROWB + c8 * 16;
        CP_ASYNC16(d, g);
    }
}

__global__ __launch_bounds__(256, 2) void attn_kernel()
{
    extern __shared__ __align__(16) char smem[];
    const uint32_t sb = smem_to_u32(smem);
    const int tid = threadIdx.x;
    const int wid = tid >> 5, lane = tid & 31;
    const int split = blockIdx.x >> 6;
    const int b = (blockIdx.x >> 5) & 1;
    const int n0 = (blockIdx.x & 31) * 128;
    const int kv0 = b * NPOS + split * 1024;
    const int r0 = wid << 4;

    // stage Q (hi at 0, lo at 18432), then ldmatrix into registers
#pragma unroll
    for (int i = 0; i < 8; i++) {
        int idx = tid + i * 256;
        int m = idx >> 10;
        int r = (idx >> 3) & 127, c8 = idx & 7;
        const __nv_bfloat16* src = m ? g_kl : g_kh;
        const char* g = (const char*)(src + (size_t)(b * NPOS + n0 + r) * 64 + c8 * 8);
        CP_ASYNC16(sb + m * 18432 + r * ROWB + c8 * 16, g);
    }
    CP_COMMIT(); CP_WAIT(0);
    __syncthreads();

    uint32_t qh[4][4], ql[4][4];
#pragma unroll
    for (int kt = 0; kt < 4; kt++) {
        uint32_t a = sb + (r0 + (lane & 15)) * ROWB + (16 * kt + ((lane >> 4) << 3)) * 2;
        LDSM_X4(qh[kt], a);
        LDSM_X4(ql[kt], a + 18432);
    }
    __syncthreads();

    float o[8][4];
#pragma unroll
    for (int i = 0; i < 8; i++)
#pragma unroll
        for (int j = 0; j < 4; j++) o[i][j] = 0.f;
    float l0 = 0.f, l1 = 0.f, m0 = -1e30f, m1 = -1e30f;

    load_tile(sb, 0, kv0, tid);
    CP_COMMIT();

    for (int t = 0; t < 16; t++) {
        __syncthreads();
        if (t + 1 < 16) {
            load_tile(sb, (t + 1) & 1, kv0 + (t + 1) * 64, tid);
            CP_COMMIT(); CP_WAIT(1);
        } else CP_WAIT(0);
        __syncthreads();

        const uint32_t base = sb + (t & 1) * BUFB;

#pragma unroll
        for (int j = 0; j < 4; j++) {
            float c0[4] = {0.f, 0.f, 0.f, 0.f}, c1[4] = {0.f, 0.f, 0.f, 0.f};
            uint32_t arow0 = base + (16 * j + (lane & 7)) * ROWB + ((lane >> 3) & 3) * 16;
            uint32_t arow1 = arow0 + 8 * ROWB;
#pragma unroll
            for (int kp = 0; kp < 2; kp++) {
                uint32_t bh[4], bl[4];
                LDSM_X4(bh, arow0 + kp * 64);
                LDSM_X4(bl, arow0 + kp * 64 + MATB);
                MMA_BF16(c0, qh[2 * kp], bh[0], bh[1]);
                MMA_BF16(c0, ql[2 * kp], bh[0], bh[1]);
                MMA_BF16(c0, qh[2 * kp], bl[0], bl[1]);
                MMA_BF16(c0, qh[2 * kp + 1], bh[2], bh[3]);
                MMA_BF16(c0, ql[2 * kp + 1], bh[2], bh[3]);
                MMA_BF16(c0, qh[2 * kp + 1], bl[2], bl[3]);
                LDSM_X4(bh, arow1 + kp * 64);
                LDSM_X4(bl, arow1 + kp * 64 + MATB);
                MMA_BF16(c1, qh[2 * kp], bh[0], bh[1]);
                MMA_BF16(c1, ql[2 * kp], bh[0], bh[1]);
                MMA_BF16(c1, qh[2 * kp], bl[0], bl[1]);
                MMA_BF16(c1, qh[2 * kp + 1], bh[2], bh[3]);
                MMA_BF16(c1, ql[2 * kp + 1], bh[2], bh[3]);
                MMA_BF16(c1, qh[2 * kp + 1], bl[2], bl[3]);
            }
            // online max update (rows: lane>>2 and lane>>2+8)
            float jm0 = fmaxf(fmaxf(c0[0], c0[1]), fmaxf(c1[0], c1[1]));
            float jm1 = fmaxf(fmaxf(c0[2], c0[3]), fmaxf(c1[2], c1[3]));
            jm0 = fmaxf(jm0, __shfl_xor_sync(0xffffffffu, jm0, 1));
            jm0 = fmaxf(jm0, __shfl_xor_sync(0xffffffffu, jm0, 2));
            jm1 = fmaxf(jm1, __shfl_xor_sync(0xffffffffu, jm1, 1));
            jm1 = fmaxf(jm1, __shfl_xor_sync(0xffffffffu, jm1, 2));
            float m0n = fmaxf(m0, jm0), m1n = fmaxf(m1, jm1);
            float s0 = __expf(m0 - m0n), s1 = __expf(m1 - m1n);
            m0 = m0n; m1 = m1n;
            float p00 = __expf(c0[0] - m0), p01 = __expf(c0[1] - m0);
            float p02 = __expf(c0[2] - m1), p03 = __expf(c0[3] - m1);
            float p10 = __expf(c1[0] - m0), p11 = __expf(c1[1] - m0);
            float p12 = __expf(c1[2] - m1), p13 = __expf(c1[3] - m1);
            l0 = l0 * s0 + (p00 + p01) + (p10 + p11);
            l1 = l1 * s1 + (p02 + p03) + (p12 + p13);
            uint32_t ph[4];
            ph[0] = pack_h2(p00, p01);
            ph[1] = pack_h2(p02, p03);
            ph[2] = pack_h2(p10, p11);
            ph[3] = pack_h2(p12, p13);
#pragma unroll
            for (int dt = 0; dt < 8; dt++) {
                o[dt][0] *= s0; o[dt][1] *= s0;
                o[dt][2] *= s1; o[dt][3] *= s1;
            }
#pragma unroll
            for (int dp = 0; dp < 4; dp++) {
                uint32_t av = base + 2 * MATB + (16 * j + (lane & 15)) * ROWB
                              + dp * 32 + ((lane >> 4) & 1) * 16;
                uint32_t vh[4], vl[4];
                LDSM_X4T(vh, av);
                LDSM_X4T(vl, av + MATB);
                MMA_FP16(o[2 * dp], ph, vh[0], vh[1]);
                MMA_FP16(o[2 * dp], ph, vl[0], vl[1]);
                MMA_FP16(o[2 * dp + 1], ph, vh[2], vh[3]);
                MMA_FP16(o[2 * dp + 1], ph, vl[2], vl[3]);
            }
        }
    }

    l0 += __shfl_xor_sync(0xffffffffu, l0, 1);
    l0 += __shfl_xor_sync(0xffffffffu, l0, 2);
    l1 += __shfl_xor_sync(0xffffffffu, l1, 1);
    l1 += __shfl_xor_sync(0xffffffffu, l1, 2);

    const int rg = b * NPOS + n0 + r0 + (lane >> 2);
    float* dst = g_opart + (size_t)split * NROWS * 64;
#pragma unroll
    for (int dt = 0; dt < 8; dt++) {
        ((float2*)(dst + (size_t)rg * 64 + dt * 8))[lane & 3] =
            make_float2(o[dt][0], o[dt][1]);
        ((float2*)(dst + (size_t)(rg + 8) * 64 + dt * 8))[lane & 3] =
            make_float2(o[dt][2], o[dt][3]);
    }
    if ((lane & 3) == 0) {
        g_lpart[split * NROWS + rg] = l0;
        g_lpart[split * NROWS + rg + 8] = l1;
        g_mpart[split * NROWS + rg] = m0;
        g_mpart[split * NROWS + rg + 8] = m1;
    }
}

// ====== Kernel 3: merge 4 splits (log-sum-exp) + outproj via mma + BN ======
// Grid 128 x 64 rows; 8 warps = 4 rowgrp x 2 colgrp(128 cols = 16 n8).
#define OASZ 9216
#define OBSZ 36864

__global__ __launch_bounds__(256, 1) void outproj_mma(
    const float* __restrict__ gamma, const float* __restrict__ beta,
    float* __restrict__ out)
{
    extern __shared__ __align__(16) char smem[];
    const uint32_t sb = smem_to_u32(smem);
    const int tid = threadIdx.x;
    const int wid = tid >> 5, lane = tid & 31;
    const int rg = wid & 3, cg = wid >> 2;
    const int row0 = blockIdx.x * 64;

    // stage B (Wo^T split) via cp.async
#pragma unroll
    for (int i = 0; i < 16; i++) {
        int idx = tid + i * 256;
        int hl = idx >> 11, jj = idx & 2047;
        int r = jj >> 3, c = jj & 7;
        const __nv_bfloat16* src = (hl ? g_wotl : g_woth) + (size_t)r * 64 + c * 8;
        CP_ASYNC16(sb + 2 * OASZ + hl * OBSZ + r * ROWB + c * 16, (const char*)src);
    }
    CP_COMMIT();

    // stage A: merge 4 split-KV partials with log-sum-exp weights, split to bf16
    {
        int r = tid >> 2, cq = tid & 3;
        int rgr = row0 + r;
        float ms[4], w[4];
        float M = -1e30f;
#pragma unroll
        for (int s = 0; s < 4; s++) {
            ms[s] = g_mpart[s * NROWS + rgr];
            M = fmaxf(M, ms[s]);
        }
        float denom = 0.f;
#pragma unroll
        for (int s = 0; s < 4; s++) {
            w[s] = __expf(ms[s] - M);
            denom += w[s] * g_lpart[s * NROWS + rgr];
        }
        float inv = 1.f / denom;
#pragma unroll
        for (int e = 0; e < 4; e++) {
            int c4 = cq * 4 + e;
            float4 u = make_float4(0.f, 0.f, 0.f, 0.f);
#pragma unroll
            for (int s = 0; s < 4; s++) {
                float4 p = ((const float4*)(g_opart + (size_t)s * NROWS * 64
                                            + (size_t)rgr * 64))[c4];
                u.x += w[s] * p.x; u.y += w[s] * p.y;
                u.z += w[s] * p.z; u.w += w[s] * p.w;
            }
            u.x *= inv; u.y *= inv; u.z *= inv; u.w *= inv;
            uint32_t h0, lo0, h1, lo1;
            split2pack(u.x, u.y, h0, lo0);
            split2pack(u.z, u.w, h1, lo1);
            *(uint2*)(smem + r * ROWB + c4 * 8) = make_uint2(h0, h1);
            *(uint2*)(smem + OASZ + r * ROWB + c4 * 8) = make_uint2(lo0, lo1);
        }
    }
    CP_WAIT(0);
    __syncthreads();

    uint32_t ah[4][4], al[4][4];
#pragma unroll
    for (int kt = 0; kt < 4; kt++) {
        uint32_t a = sb + (16 * rg + (lane & 15)) * ROWB + kt * 32 + ((lane >> 4) << 4);
        LDSM_X4(ah[kt], a);
        LDSM_X4(al[kt], a + OASZ);
    }

    float acc[16][4];
#pragma unroll
    for (int t = 0; t < 16; t++)
#pragma unroll
        for (int j = 0; j < 4; j++) acc[t][j] = 0.f;

#pragma unroll
    for (int t = 0; t < 16; t++) {
        int nrow0 = cg * 128 + t * 8;
#pragma unroll
        for (int kp = 0; kp < 2; kp++) {
            uint32_t bh[4], bl[4];
            uint32_t ba = sb + 2 * OASZ + (nrow0 + (lane & 7)) * ROWB
                          + kp * 64 + ((lane >> 3) & 3) * 16;
            LDSM_X4(bh, ba);
            LDSM_X4(bl, ba + OBSZ);
            MMA_BF16(acc[t], ah[2 * kp], bh[0], bh[1]);
            MMA_BF16(acc[t], al[2 * kp], bh[0], bh[1]);
            MMA_BF16(acc[t], ah[2 * kp], bl[0], bl[1]);
            MMA_BF16(acc[t], ah[2 * kp + 1], bh[2], bh[3]);
            MMA_BF16(acc[t], al[2 * kp + 1], bh[2], bh[3]);
            MMA_BF16(acc[t], ah[2 * kp + 1], bl[2], bl[3]);
        }
    }

    const float sc = rsqrtf(1.0f + 1e-3f);
    const int r1 = row0 + 16 * rg + (lane >> 2);
#pragma unroll
    for (int t = 0; t < 16; t++) {
        int col = cg * 128 + t * 8 + (lane & 3) * 2;
        float g0 = __ldg(gamma + col) * sc, g1 = __ldg(gamma + col + 1) * sc;
        float b0 = __ldg(beta + col), b1 = __ldg(beta + col + 1);
        *(float2*)(out + (size_t)r1 * 256 + col) =
            make_float2(fmaf(acc[t][0], g0, b0), fmaf(acc[t][1], g1, b1));
        *(float2*)(out + (size_t)(r1 + 8) * 256 + col) =
            make_float2(fmaf(acc[t][2], g0, b0), fmaf(acc[t][3], g1, b1));
    }
}

extern "C" void kernel_launch(void* const* d_in, const int* in_sizes, int n_in,
                              void* d_out, int out_size) {
    const float* x     = (const float*)d_in[0];
    const float* Wk    = (const float*)d_in[1];
    const float* Wq    = (const float*)d_in[2];
    const float* Wv    = (const float*)d_in[3];
    const float* Wo    = (const float*)d_in[4];
    const float* gamma = (const float*)d_in[5];
    const float* beta  = (const float*)d_in[6];
    float* out = (float*)d_out;

    cudaFuncSetAttribute(proj_mma, cudaFuncAttributeMaxDynamicSharedMemorySize, 2 * PBUF);
    cudaFuncSetAttribute(attn_kernel, cudaFuncAttributeMaxDynamicSharedMemorySize, 2 * BUFB);
    cudaFuncSetAttribute(outproj_mma, cudaFuncAttributeMaxDynamicSharedMemorySize,
                         2 * OASZ + 2 * OBSZ);

    split_w_kernel<<<256, 256>>>(Wk, Wq, Wv, Wo);
    proj_mma<<<256, 256, 2 * PBUF>>>(x);
    attn_kernel<<<256, 256, 2 * BUFB>>>();
    outproj_mma<<<128, 256, 2 * OASZ + 2 * OBSZ>>>(gamma, beta, out);
}

// round 14
// speedup vs baseline: 1.1964x; 1.1353x over previous
#include <cuda_runtime.h>
#include <cuda_bf16.h>
#include <cuda_fp16.h>
#include <cstdint>

#define NPOS 4096
#define NROWS 8192

// ---- scratch (device globals; allocation-free rule) ----
__device__ __align__(16) __nv_bfloat16 g_wth[192 * 256], g_wtl[192 * 256];   // [3*64 n][256 k]
__device__ __align__(16) __nv_bfloat16 g_woth[256 * 64], g_wotl[256 * 64];   // [256 n][64 k]
__device__ __align__(16) __nv_bfloat16 g_kh[NROWS * 64], g_kl[NROWS * 64];   // flash-Q role (bf16)
__device__ __align__(16) __nv_bfloat16 g_qh[NROWS * 64], g_ql[NROWS * 64];   // flash-K role (bf16)
__device__ __align__(16) __half        g_vh[NROWS * 64];                     // V (fp16)
__device__ __align__(16) float g_opart[4 * NROWS * 64];  // [split][row][d]
__device__ __align__(16) float g_lpart[4 * NROWS];       // [split][row]
__device__ __align__(16) float g_mpart[4 * NROWS];       // [split][row]

__device__ __forceinline__ uint32_t smem_to_u32(const void* p) {
    uint32_t a;
    asm("{ .reg .u64 t; cvta.to.shared.u64 t, %1; cvt.u32.u64 %0, t; }" : "=r"(a) : "l"(p));
    return a;
}
#define CP_ASYNC16(dst, src) asm volatile( \
    "cp.async.cg.shared.global [%0], [%1], 16;" :: "r"(dst), "l"(src) : "memory")
#define CP_COMMIT() asm volatile("cp.async.commit_group;" ::: "memory")
#define CP_WAIT(N)  asm volatile("cp.async.wait_group %0;" :: "n"(N) : "memory")

#define LDSM_X4(r, a) asm volatile( \
    "ldmatrix.sync.aligned.m8n8.x4.shared.b16 {%0,%1,%2,%3}, [%4];" \
    : "=r"((r)[0]), "=r"((r)[1]), "=r"((r)[2]), "=r"((r)[3]) : "r"(a))
#define LDSM_X4T(r, a) asm volatile( \
    "ldmatrix.sync.aligned.m8n8.x4.trans.shared.b16 {%0,%1,%2,%3}, [%4];" \
    : "=r"((r)[0]), "=r"((r)[1]), "=r"((r)[2]), "=r"((r)[3]) : "r"(a))
#define MMA_BF16(c, a, b0, b1) asm volatile( \
    "mma.sync.aligned.m16n8k16.row.col.f32.bf16.bf16.f32 " \
    "{%0,%1,%2,%3}, {%4,%5,%6,%7}, {%8,%9}, {%0,%1,%2,%3};" \
    : "+f"((c)[0]), "+f"((c)[1]), "+f"((c)[2]), "+f"((c)[3]) \
    : "r"((a)[0]), "r"((a)[1]), "r"((a)[2]), "r"((a)[3]), "r"(b0), "r"(b1))
#define MMA_FP16(c, a, b0, b1) asm volatile( \
    "mma.sync.aligned.m16n8k16.row.col.f32.f16.f16.f32 " \
    "{%0,%1,%2,%3}, {%4,%5,%6,%7}, {%8,%9}, {%0,%1,%2,%3};" \
    : "+f"((c)[0]), "+f"((c)[1]), "+f"((c)[2]), "+f"((c)[3]) \
    : "r"((a)[0]), "r"((a)[1]), "r"((a)[2]), "r"((a)[3]), "r"(b0), "r"(b1))

__device__ __forceinline__ void split2pack(float a, float b, uint32_t& hi, uint32_t& lo) {
    __nv_bfloat16 h0 = __float2bfloat16(a), h1 = __float2bfloat16(b);
    __nv_bfloat162 hh = __halves2bfloat162(h0, h1);
    __nv_bfloat162 ll = __floats2bfloat162_rn(a - __bfloat162float(h0),
                                              b - __bfloat162float(h1));
    hi = *(uint32_t*)&hh; lo = *(uint32_t*)&ll;
}
__device__ __forceinline__ uint32_t pack_h2(float a, float b) {
    __half2 h = __floats2half2_rn(a, b);
    return *(uint32_t*)&h;
}

// ============ Kernel 0: transpose+split W (192x256) and Wo (256x64) ============
__global__ __launch_bounds__(256) void split_w_kernel(
    const float* __restrict__ Wk, const float* __restrict__ Wq,
    const float* __restrict__ Wv, const float* __restrict__ Wo)
{
    const int bid = blockIdx.x, tid = threadIdx.x;
    if (bid < 192) {
        int j = bid * 256 + tid;
        int m = j >> 14, rem = j & 16383;
        int k = rem >> 6, n = rem & 63;
        const float* W = (m == 0) ? Wk : (m == 1) ? Wq : Wv;
        float v = W[k * 64 + n];
        __nv_bfloat16 h = __float2bfloat16(v);
        int di = (m * 64 + n) * 256 + k;
        g_wth[di] = h;
        g_wtl[di] = __float2bfloat16(v - __bfloat162float(h));
    } else {
        int j = (bid - 192) * 256 + tid;
        int k = j >> 8, n = j & 255;
        float v = Wo[k * 256 + n];
        __nv_bfloat16 h = __float2bfloat16(v);
        g_woth[n * 64 + k] = h;
        g_wotl[n * 64 + k] = __float2bfloat16(v - __bfloat162float(h));
    }
}

// ============ Kernel 1: fused x-split + proj mma: [8192,256]@[256,192] ============
#define PSTG 4096
#define PASZ 2560
#define PBSZ 15360
#define PBUF 39936

__device__ __forceinline__ void proj_load(uint32_t sb, int buf, int row0, int k0, int tid,
                                          const float* __restrict__ x) {
    {
        int r = tid >> 3, c4 = tid & 7;
        const char* g = (const char*)(x + (size_t)(row0 + r) * 256 + k0 + c4 * 4);
        CP_ASYNC16(sb + buf * PBUF + r * 128 + c4 * 16, g);
    }
#pragma unroll
    for (int i = 0; i < 6; i++) {
        int j = tid + i * 256;
        int hl = j >= 768; int jj = j - (hl ? 768 : 0);
        int r = jj >> 2, c = jj & 3;
        const __nv_bfloat16* src = (hl ? g_wtl : g_wth) + (size_t)r * 256 + k0 + c * 8;
        CP_ASYNC16(sb + buf * PBUF + PSTG + 2 * PASZ + hl * PBSZ + r * 80 + c * 16,
                   (const char*)src);
    }
}

__global__ __launch_bounds__(256, 1) void proj_mma(const float* __restrict__ x)
{
    extern __shared__ __align__(16) char smem[];
    const uint32_t sb = smem_to_u32(smem);
    const int tid = threadIdx.x;
    const int wid = tid >> 5, lane = tid & 31;
    const int rg = wid & 1, cg = wid >> 1;
    const int row0 = blockIdx.x * 32;

    float c[6][4];
#pragma unroll
    for (int t = 0; t < 6; t++)
#pragma unroll
        for (int j = 0; j < 4; j++) c[t][j] = 0.f;

    proj_load(sb, 0, row0, 0, tid, x);
    CP_COMMIT();

    for (int ch = 0; ch < 8; ch++) {
        __syncthreads();
        if (ch + 1 < 8) {
            proj_load(sb, (ch + 1) & 1, row0, (ch + 1) * 32, tid, x);
            CP_COMMIT(); CP_WAIT(1);
        } else CP_WAIT(0);
        __syncthreads();

        const uint32_t base = sb + (ch & 1) * PBUF;
        {
            int r = tid >> 3, cc = (tid & 7) * 4;
            float4 v = *(const float4*)(smem + (ch & 1) * PBUF + r * 128 + cc * 4);
            uint32_t h0, l0, h1, l1;
            split2pack(v.x, v.y, h0, l0);
            split2pack(v.z, v.w, h1, l1);
            *(uint2*)(smem + (ch & 1) * PBUF + PSTG + r * 80 + cc * 2) = make_uint2(h0, h1);
            *(uint2*)(smem + (ch & 1) * PBUF + PSTG + PASZ + r * 80 + cc * 2) = make_uint2(l0, l1);
        }
        __syncthreads();

        uint32_t ah[2][4], al[2][4];
#pragma unroll
        for (int kt = 0; kt < 2; kt++) {
            uint32_t a = base + PSTG + (16 * rg + (lane & 15)) * 80 + kt * 32 + ((lane >> 4) << 4);
            LDSM_X4(ah[kt], a);
            LDSM_X4(al[kt], a + PASZ);
        }
#pragma unroll
        for (int t = 0; t < 6; t++) {
            int g = cg * 6 + t;
            uint32_t bh[4], bl[4];
            uint32_t ba = base + PSTG + 2 * PASZ + (8 * g + (lane & 7)) * 80 + ((lane >> 3) & 3) * 16;
            LDSM_X4(bh, ba);
            LDSM_X4(bl, ba + PBSZ);
            MMA_BF16(c[t], ah[0], bh[0], bh[1]);
            MMA_BF16(c[t], al[0], bh[0], bh[1]);
            MMA_BF16(c[t], ah[0], bl[0], bl[1]);
            MMA_BF16(c[t], ah[1], bh[2], bh[3]);
            MMA_BF16(c[t], al[1], bh[2], bh[3]);
            MMA_BF16(c[t], ah[1], bl[2], bl[3]);
        }
    }

    uint32_t* hip[3] = { (uint32_t*)g_kh, (uint32_t*)g_qh, (uint32_t*)g_vh };
    uint32_t* lop[2] = { (uint32_t*)g_kl, (uint32_t*)g_ql };
    const int r1 = row0 + 16 * rg + (lane >> 2);
#pragma unroll
    for (int t = 0; t < 6; t++) {
        int g = cg * 6 + t;
        int mat = g >> 3, cu = (g & 7) * 4 + (lane & 3);
        if (mat == 2) {   // V: single fp16
            hip[2][(size_t)r1 * 32 + cu] = pack_h2(c[t][0], c[t][1]);
            hip[2][(size_t)(r1 + 8) * 32 + cu] = pack_h2(c[t][2], c[t][3]);
        } else {
            uint32_t h0, l0, h1, l1;
            split2pack(c[t][0], c[t][1], h0, l0);
            split2pack(c[t][2], c[t][3], h1, l1);
            hip[mat][(size_t)r1 * 32 + cu] = h0;
            lop[mat][(size_t)r1 * 32 + cu] = l0;
            hip[mat][(size_t)(r1 + 8) * 32 + cu] = h1;
            lop[mat][(size_t)(r1 + 8) * 32 + cu] = l1;
        }
    }
}

// ========== Kernel 2: mma.sync flash attention (per-tile hoisted max) ==========
// Grid 256 = [split4][batch2][qblock32]; 16 KV tiles/CTA.
// SMEM buf: {Kh, Kl, Vh} each 64x144B = 27648 B; double buffered.
#define ROWB 144
#define MATB 9216
#define BUFB 27648

__device__ __forceinline__ void load_tile(uint32_t sb, int buf, int grow0, int tid) {
    const char* srcs[3] = { (const char*)g_qh, (const char*)g_ql, (const char*)g_vh };
#pragma unroll
    for (int i = 0; i < 6; i++) {
        int idx = tid + i * 256;
        int mat = idx >> 9;
        int r = (idx >> 3) & 63, c8 = idx & 7;
        const char* g = srcs[mat] + ((size_t)(grow0 + r) * 64 + c8 * 8) * 2;
        uint32_t d = sb + buf * BUFB + mat * MATB + r * ROWB + c8 * 16;
        CP_ASYNC16(d, g);
    }
}

__global__ __launch_bounds__(256, 1) void attn_kernel()
{
    extern __shared__ __align__(16) char smem[];
    const uint32_t sb = smem_to_u32(smem);
    const int tid = threadIdx.x;
    const int wid = tid >> 5, lane = tid & 31;
    const int split = blockIdx.x >> 6;
    const int b = (blockIdx.x >> 5) & 1;
    const int n0 = (blockIdx.x & 31) * 128;
    const int kv0 = b * NPOS + split * 1024;
    const int r0 = wid << 4;

    // stage Q (hi at 0, lo at 18432), then ldmatrix into registers
#pragma unroll
    for (int i = 0; i < 8; i++) {
        int idx = tid + i * 256;
        int m = idx >> 10;
        int r = (idx >> 3) & 127, c8 = idx & 7;
        const __nv_bfloat16* src = m ? g_kl : g_kh;
        const char* g = (const char*)(src + (size_t)(b * NPOS + n0 + r) * 64 + c8 * 8);
        CP_ASYNC16(sb + m * 18432 + r * ROWB + c8 * 16, g);
    }
    CP_COMMIT(); CP_WAIT(0);
    __syncthreads();

    uint32_t qh[4][4], ql[4][4];
#pragma unroll
    for (int kt = 0; kt < 4; kt++) {
        uint32_t a = sb + (r0 + (lane & 15)) * ROWB + (16 * kt + ((lane >> 4) << 3)) * 2;
        LDSM_X4(qh[kt], a);
        LDSM_X4(ql[kt], a + 18432);
    }
    __syncthreads();

    float o[8][4];
#pragma unroll
    for (int i = 0; i < 8; i++)
#pragma unroll
        for (int j = 0; j < 4; j++) o[i][j] = 0.f;
    float l0 = 0.f, l1 = 0.f, m0 = -1e30f, m1 = -1e30f;

    load_tile(sb, 0, kv0, tid);
    CP_COMMIT();

    for (int t = 0; t < 16; t++) {
        __syncthreads();
        if (t + 1 < 16) {
            load_tile(sb, (t + 1) & 1, kv0 + (t + 1) * 64, tid);
            CP_COMMIT(); CP_WAIT(1);
        } else CP_WAIT(0);
        __syncthreads();

        const uint32_t base = sb + (t & 1) * BUFB;

        // ---- Phase 1: all S for the tile (8 independent MMA chains) ----
        float cs[4][8];
#pragma unroll
        for (int j = 0; j < 4; j++) {
#pragma unroll
            for (int e = 0; e < 8; e++) cs[j][e] = 0.f;
            uint32_t arow0 = base + (16 * j + (lane & 7)) * ROWB + ((lane >> 3) & 3) * 16;
            uint32_t arow1 = arow0 + 8 * ROWB;
#pragma unroll
            for (int kp = 0; kp < 2; kp++) {
                uint32_t bh[4], bl[4];
                LDSM_X4(bh, arow0 + kp * 64);
                LDSM_X4(bl, arow0 + kp * 64 + MATB);
                MMA_BF16(&cs[j][0], qh[2 * kp], bh[0], bh[1]);
                MMA_BF16(&cs[j][0], ql[2 * kp], bh[0], bh[1]);
                MMA_BF16(&cs[j][0], qh[2 * kp], bl[0], bl[1]);
                MMA_BF16(&cs[j][0], qh[2 * kp + 1], bh[2], bh[3]);
                MMA_BF16(&cs[j][0], ql[2 * kp + 1], bh[2], bh[3]);
                MMA_BF16(&cs[j][0], qh[2 * kp + 1], bl[2], bl[3]);
                LDSM_X4(bh, arow1 + kp * 64);
                LDSM_X4(bl, arow1 + kp * 64 + MATB);
                MMA_BF16(&cs[j][4], qh[2 * kp], bh[0], bh[1]);
                MMA_BF16(&cs[j][4], ql[2 * kp], bh[0], bh[1]);
                MMA_BF16(&cs[j][4], qh[2 * kp], bl[0], bl[1]);
                MMA_BF16(&cs[j][4], qh[2 * kp + 1], bh[2], bh[3]);
                MMA_BF16(&cs[j][4], ql[2 * kp + 1], bh[2], bh[3]);
                MMA_BF16(&cs[j][4], qh[2 * kp + 1], bl[2], bl[3]);
            }
        }

        // ---- Phase 2: per-tile max, rescale ----
        float jm0 = -1e30f, jm1 = -1e30f;
#pragma unroll
        for (int j = 0; j < 4; j++) {
            jm0 = fmaxf(jm0, fmaxf(fmaxf(cs[j][0], cs[j][1]), fmaxf(cs[j][4], cs[j][5])));
            jm1 = fmaxf(jm1, fmaxf(fmaxf(cs[j][2], cs[j][3]), fmaxf(cs[j][6], cs[j][7])));
        }
        jm0 = fmaxf(jm0, __shfl_xor_sync(0xffffffffu, jm0, 1));
        jm0 = fmaxf(jm0, __shfl_xor_sync(0xffffffffu, jm0, 2));
        jm1 = fmaxf(jm1, __shfl_xor_sync(0xffffffffu, jm1, 1));
        jm1 = fmaxf(jm1, __shfl_xor_sync(0xffffffffu, jm1, 2));
        float m0n = fmaxf(m0, jm0), m1n = fmaxf(m1, jm1);
        float s0 = __expf(m0 - m0n), s1 = __expf(m1 - m1n);
        m0 = m0n; m1 = m1n;
        l0 *= s0; l1 *= s1;
#pragma unroll
        for (int dt = 0; dt < 8; dt++) {
            o[dt][0] *= s0; o[dt][1] *= s0;
            o[dt][2] *= s1; o[dt][3] *= s1;
        }

        // ---- Phase 3: exp + PV per j ----
#pragma unroll
        for (int j = 0; j < 4; j++) {
            float p00 = __expf(cs[j][0] - m0), p01 = __expf(cs[j][1] - m0);
            float p02 = __expf(cs[j][2] - m1), p03 = __expf(cs[j][3] - m1);
            float p10 = __expf(cs[j][4] - m0), p11 = __expf(cs[j][5] - m0);
            float p12 = __expf(cs[j][6] - m1), p13 = __expf(cs[j][7] - m1);
            l0 += (p00 + p01) + (p10 + p11);
            l1 += (p02 + p03) + (p12 + p13);
            uint32_t ph[4];
            ph[0] = pack_h2(p00, p01);
            ph[1] = pack_h2(p02, p03);
            ph[2] = pack_h2(p10, p11);
            ph[3] = pack_h2(p12, p13);
#pragma unroll
            for (int dp = 0; dp < 4; dp++) {
                uint32_t av = base + 2 * MATB + (16 * j + (lane & 15)) * ROWB
                              + dp * 32 + ((lane >> 4) & 1) * 16;
                uint32_t vh[4];
                LDSM_X4T(vh, av);
                MMA_FP16(o[2 * dp], ph, vh[0], vh[1]);
                MMA_FP16(o[2 * dp + 1], ph, vh[2], vh[3]);
            }
        }
    }

    l0 += __shfl_xor_sync(0xffffffffu, l0, 1);
    l0 += __shfl_xor_sync(0xffffffffu, l0, 2);
    l1 += __shfl_xor_sync(0xffffffffu, l1, 1);
    l1 += __shfl_xor_sync(0xffffffffu, l1, 2);

    const int rg = b * NPOS + n0 + r0 + (lane >> 2);
    float* dst = g_opart + (size_t)split * NROWS * 64;
#pragma unroll
    for (int dt = 0; dt < 8; dt++) {
        ((float2*)(dst + (size_t)rg * 64 + dt * 8))[lane & 3] =
            make_float2(o[dt][0], o[dt][1]);
        ((float2*)(dst + (size_t)(rg + 8) * 64 + dt * 8))[lane & 3] =
            make_float2(o[dt][2], o[dt][3]);
    }
    if ((lane & 3) == 0) {
        g_lpart[split * NROWS + rg] = l0;
        g_lpart[split * NROWS + rg + 8] = l1;
        g_mpart[split * NROWS + rg] = m0;
        g_mpart[split * NROWS + rg + 8] = m1;
    }
}

// ====== Kernel 3: merge 4 splits (log-sum-exp) + outproj via mma + BN ======
#define OASZ 9216
#define OBSZ 36864

__global__ __launch_bounds__(256, 1) void outproj_mma(
    const float* __restrict__ gamma, const float* __restrict__ beta,
    float* __restrict__ out)
{
    extern __shared__ __align__(16) char smem[];
    const uint32_t sb = smem_to_u32(smem);
    const int tid = threadIdx.x;
    const int wid = tid >> 5, lane = tid & 31;
    const int rg = wid & 3, cg = wid >> 2;
    const int row0 = blockIdx.x * 64;

#pragma unroll
    for (int i = 0; i < 16; i++) {
        int idx = tid + i * 256;
        int hl = idx >> 11, jj = idx & 2047;
        int r = jj >> 3, c = jj & 7;
        const __nv_bfloat16* src = (hl ? g_wotl : g_woth) + (size_t)r * 64 + c * 8;
        CP_ASYNC16(sb + 2 * OASZ + hl * OBSZ + r * ROWB + c * 16, (const char*)src);
    }
    CP_COMMIT();

    {
        int r = tid >> 2, cq = tid & 3;
        int rgr = row0 + r;
        float ms[4], w[4];
        float M = -1e30f;
#pragma unroll
        for (int s = 0; s < 4; s++) {
            ms[s] = g_mpart[s * NROWS + rgr];
            M = fmaxf(M, ms[s]);
        }
        float denom = 0.f;
#pragma unroll
        for (int s = 0; s < 4; s++) {
            w[s] = __expf(ms[s] - M);
            denom += w[s] * g_lpart[s * NROWS + rgr];
        }
        float inv = 1.f / denom;
#pragma unroll
        for (int e = 0; e < 4; e++) {
            int c4 = cq * 4 + e;
            float4 u = make_float4(0.f, 0.f, 0.f, 0.f);
#pragma unroll
            for (int s = 0; s < 4; s++) {
                float4 p = ((const float4*)(g_opart + (size_t)s * NROWS * 64
                                            + (size_t)rgr * 64))[c4];
                u.x += w[s] * p.x; u.y += w[s] * p.y;
                u.z += w[s] * p.z; u.w += w[s] * p.w;
            }
            u.x *= inv; u.y *= inv; u.z *= inv; u.w *= inv;
            uint32_t h0, lo0, h1, lo1;
            split2pack(u.x, u.y, h0, lo0);
            split2pack(u.z, u.w, h1, lo1);
            *(uint2*)(smem + r * ROWB + c4 * 8) = make_uint2(h0, h1);
            *(uint2*)(smem + OASZ + r * ROWB + c4 * 8) = make_uint2(lo0, lo1);
        }
    }
    CP_WAIT(0);
    __syncthreads();

    uint32_t ah[4][4], al[4][4];
#pragma unroll
    for (int kt = 0; kt < 4; kt++) {
        uint32_t a = sb + (16 * rg + (lane & 15)) * ROWB + kt * 32 + ((lane >> 4) << 4);
        LDSM_X4(ah[kt], a);
        LDSM_X4(al[kt], a + OASZ);
    }

    float acc[16][4];
#pragma unroll
    for (int t = 0; t < 16; t++)
#pragma unroll
        for (int j = 0; j < 4; j++) acc[t][j] = 0.f;

#pragma unroll
    for (int t = 0; t < 16; t++) {
        int nrow0 = cg * 128 + t * 8;
#pragma unroll
        for (int kp = 0; kp < 2; kp++) {
            uint32_t bh[4], bl[4];
            uint32_t ba = sb + 2 * OASZ + (nrow0 + (lane & 7)) * ROWB
                          + kp * 64 + ((lane >> 3) & 3) * 16;
            LDSM_X4(bh, ba);
            LDSM_X4(bl, ba + OBSZ);
            MMA_BF16(acc[t], ah[2 * kp], bh[0], bh[1]);
            MMA_BF16(acc[t], al[2 * kp], bh[0], bh[1]);
            MMA_BF16(acc[t], ah[2 * kp], bl[0], bl[1]);
            MMA_BF16(acc[t], ah[2 * kp + 1], bh[2], bh[3]);
            MMA_BF16(acc[t], al[2 * kp + 1], bh[2], bh[3]);
            MMA_BF16(acc[t], ah[2 * kp + 1], bl[2], bl[3]);
        }
    }

    const float sc = rsqrtf(1.0f + 1e-3f);
    const int r1 = row0 + 16 * rg + (lane >> 2);
#pragma unroll
    for (int t = 0; t < 16; t++) {
        int col = cg * 128 + t * 8 + (lane & 3) * 2;
        float g0 = __ldg(gamma + col) * sc, g1 = __ldg(gamma + col + 1) * sc;
        float b0 = __ldg(beta + col), b1 = __ldg(beta + col + 1);
        *(float2*)(out + (size_t)r1 * 256 + col) =
            make_float2(fmaf(acc[t][0], g0, b0), fmaf(acc[t][1], g1, b1));
        *(float2*)(out + (size_t)(r1 + 8) * 256 + col) =
            make_float2(fmaf(acc[t][2], g0, b0), fmaf(acc[t][3], g1, b1));
    }
}

extern "C" void kernel_launch(void* const* d_in, const int* in_sizes, int n_in,
                              void* d_out, int out_size) {
    const float* x     = (const float*)d_in[0];
    const float* Wk    = (const float*)d_in[1];
    const float* Wq    = (const float*)d_in[2];
    const float* Wv    = (const float*)d_in[3];
    const float* Wo    = (const float*)d_in[4];
    const float* gamma = (const float*)d_in[5];
    const float* beta  = (const float*)d_in[6];
    float* out = (float*)d_out;

    cudaFuncSetAttribute(proj_mma, cudaFuncAttributeMaxDynamicSharedMemorySize, 2 * PBUF);
    cudaFuncSetAttribute(attn_kernel, cudaFuncAttributeMaxDynamicSharedMemorySize, 2 * BUFB);
    cudaFuncSetAttribute(outproj_mma, cudaFuncAttributeMaxDynamicSharedMemorySize,
                         2 * OASZ + 2 * OBSZ);

    split_w_kernel<<<256, 256>>>(Wk, Wq, Wv, Wo);
    proj_mma<<<256, 256, 2 * PBUF>>>(x);
    attn_kernel<<<256, 256, 2 * BUFB>>>();
    outproj_mma<<<128, 256, 2 * OASZ + 2 * OBSZ>>>(gamma, beta, out);
}

// round 15
// speedup vs baseline: 1.2187x; 1.0186x over previous
#include <cuda_runtime.h>
#include <cuda_bf16.h>
#include <cuda_fp16.h>
#include <cstdint>

#define NPOS 4096
#define NROWS 8192

// ---- scratch (device globals; allocation-free rule) ----
__device__ __align__(16) __nv_bfloat16 g_wth[192 * 256], g_wtl[192 * 256];   // [3*64 n][256 k]
__device__ __align__(16) __half        g_woh[256 * 64];                      // Wo^T fp16 [256 n][64 k]
__device__ __align__(16) __nv_bfloat16 g_kh[NROWS * 64], g_kl[NROWS * 64];   // flash-Q role (bf16)
__device__ __align__(16) __nv_bfloat16 g_qh[NROWS * 64], g_ql[NROWS * 64];   // flash-K role (bf16)
__device__ __align__(16) __half        g_vh[NROWS * 64];                     // V (fp16)
__device__ __align__(16) float g_opart[4 * NROWS * 64];  // [split][row][d]
__device__ __align__(16) float g_lpart[4 * NROWS];       // [split][row]
__device__ __align__(16) float g_mpart[4 * NROWS];       // [split][row]

__device__ __forceinline__ uint32_t smem_to_u32(const void* p) {
    uint32_t a;
    asm("{ .reg .u64 t; cvta.to.shared.u64 t, %1; cvt.u32.u64 %0, t; }" : "=r"(a) : "l"(p));
    return a;
}
#define CP_ASYNC16(dst, src) asm volatile( \
    "cp.async.cg.shared.global [%0], [%1], 16;" :: "r"(dst), "l"(src) : "memory")
#define CP_COMMIT() asm volatile("cp.async.commit_group;" ::: "memory")
#define CP_WAIT(N)  asm volatile("cp.async.wait_group %0;" :: "n"(N) : "memory")

#define LDSM_X4(r, a) asm volatile( \
    "ldmatrix.sync.aligned.m8n8.x4.shared.b16 {%0,%1,%2,%3}, [%4];" \
    : "=r"((r)[0]), "=r"((r)[1]), "=r"((r)[2]), "=r"((r)[3]) : "r"(a))
#define LDSM_X4T(r, a) asm volatile( \
    "ldmatrix.sync.aligned.m8n8.x4.trans.shared.b16 {%0,%1,%2,%3}, [%4];" \
    : "=r"((r)[0]), "=r"((r)[1]), "=r"((r)[2]), "=r"((r)[3]) : "r"(a))
#define MMA_BF16(c, a, b0, b1) asm volatile( \
    "mma.sync.aligned.m16n8k16.row.col.f32.bf16.bf16.f32 " \
    "{%0,%1,%2,%3}, {%4,%5,%6,%7}, {%8,%9}, {%0,%1,%2,%3};" \
    : "+f"((c)[0]), "+f"((c)[1]), "+f"((c)[2]), "+f"((c)[3]) \
    : "r"((a)[0]), "r"((a)[1]), "r"((a)[2]), "r"((a)[3]), "r"(b0), "r"(b1))
#define MMA_FP16(c, a, b0, b1) asm volatile( \
    "mma.sync.aligned.m16n8k16.row.col.f32.f16.f16.f32 " \
    "{%0,%1,%2,%3}, {%4,%5,%6,%7}, {%8,%9}, {%0,%1,%2,%3};" \
    : "+f"((c)[0]), "+f"((c)[1]), "+f"((c)[2]), "+f"((c)[3]) \
    : "r"((a)[0]), "r"((a)[1]), "r"((a)[2]), "r"((a)[3]), "r"(b0), "r"(b1))

__device__ __forceinline__ void split2pack(float a, float b, uint32_t& hi, uint32_t& lo) {
    __nv_bfloat16 h0 = __float2bfloat16(a), h1 = __float2bfloat16(b);
    __nv_bfloat162 hh = __halves2bfloat162(h0, h1);
    __nv_bfloat162 ll = __floats2bfloat162_rn(a - __bfloat162float(h0),
                                              b - __bfloat162float(h1));
    hi = *(uint32_t*)&hh; lo = *(uint32_t*)&ll;
}
__device__ __forceinline__ uint32_t pack_h2(float a, float b) {
    __half2 h = __floats2half2_rn(a, b);
    return *(uint32_t*)&h;
}

// ============ Kernel 0: transpose+split W (192x256); Wo -> fp16 (256x64) ============
__global__ __launch_bounds__(256) void split_w_kernel(
    const float* __restrict__ Wk, const float* __restrict__ Wq,
    const float* __restrict__ Wv, const float* __restrict__ Wo)
{
    const int bid = blockIdx.x, tid = threadIdx.x;
    if (bid < 192) {
        int j = bid * 256 + tid;
        int m = j >> 14, rem = j & 16383;
        int k = rem >> 6, n = rem & 63;
        const float* W = (m == 0) ? Wk : (m == 1) ? Wq : Wv;
        float v = W[k * 64 + n];
        __nv_bfloat16 h = __float2bfloat16(v);
        int di = (m * 64 + n) * 256 + k;
        g_wth[di] = h;
        g_wtl[di] = __float2bfloat16(v - __bfloat162float(h));
    } else {
        int j = (bid - 192) * 256 + tid;
        int k = j >> 8, n = j & 255;
        g_woh[n * 64 + k] = __float2half_rn(Wo[k * 256 + n]);
    }
}

// ============ Kernel 1: fused x-split + proj mma: [8192,256]@[256,192] ============
#define PSTG 4096
#define PASZ 2560
#define PBSZ 15360
#define PBUF 39936

__device__ __forceinline__ void proj_load(uint32_t sb, int buf, int row0, int k0, int tid,
                                          const float* __restrict__ x) {
    {
        int r = tid >> 3, c4 = tid & 7;
        const char* g = (const char*)(x + (size_t)(row0 + r) * 256 + k0 + c4 * 4);
        CP_ASYNC16(sb + buf * PBUF + r * 128 + c4 * 16, g);
    }
#pragma unroll
    for (int i = 0; i < 6; i++) {
        int j = tid + i * 256;
        int hl = j >= 768; int jj = j - (hl ? 768 : 0);
        int r = jj >> 2, c = jj & 3;
        const __nv_bfloat16* src = (hl ? g_wtl : g_wth) + (size_t)r * 256 + k0 + c * 8;
        CP_ASYNC16(sb + buf * PBUF + PSTG + 2 * PASZ + hl * PBSZ + r * 80 + c * 16,
                   (const char*)src);
    }
}

__global__ __launch_bounds__(256, 2) void proj_mma(const float* __restrict__ x)
{
    extern __shared__ __align__(16) char smem[];
    const uint32_t sb = smem_to_u32(smem);
    const int tid = threadIdx.x;
    const int wid = tid >> 5, lane = tid & 31;
    const int rg = wid & 1, cg = wid >> 1;
    const int row0 = blockIdx.x * 32;

    float c[6][4];
#pragma unroll
    for (int t = 0; t < 6; t++)
#pragma unroll
        for (int j = 0; j < 4; j++) c[t][j] = 0.f;

    proj_load(sb, 0, row0, 0, tid, x);
    CP_COMMIT();

    for (int ch = 0; ch < 8; ch++) {
        __syncthreads();
        if (ch + 1 < 8) {
            proj_load(sb, (ch + 1) & 1, row0, (ch + 1) * 32, tid, x);
            CP_COMMIT(); CP_WAIT(1);
        } else CP_WAIT(0);
        __syncthreads();

        const uint32_t base = sb + (ch & 1) * PBUF;
        {
            int r = tid >> 3, cc = (tid & 7) * 4;
            float4 v = *(const float4*)(smem + (ch & 1) * PBUF + r * 128 + cc * 4);
            uint32_t h0, l0, h1, l1;
            split2pack(v.x, v.y, h0, l0);
            split2pack(v.z, v.w, h1, l1);
            *(uint2*)(smem + (ch & 1) * PBUF + PSTG + r * 80 + cc * 2) = make_uint2(h0, h1);
            *(uint2*)(smem + (ch & 1) * PBUF + PSTG + PASZ + r * 80 + cc * 2) = make_uint2(l0, l1);
        }
        __syncthreads();

        uint32_t ah[2][4], al[2][4];
#pragma unroll
        for (int kt = 0; kt < 2; kt++) {
            uint32_t a = base + PSTG + (16 * rg + (lane & 15)) * 80 + kt * 32 + ((lane >> 4) << 4);
            LDSM_X4(ah[kt], a);
            LDSM_X4(al[kt], a + PASZ);
        }
#pragma unroll
        for (int t = 0; t < 6; t++) {
            int g = cg * 6 + t;
            uint32_t bh[4], bl[4];
            uint32_t ba = base + PSTG + 2 * PASZ + (8 * g + (lane & 7)) * 80 + ((lane >> 3) & 3) * 16;
            LDSM_X4(bh, ba);
            LDSM_X4(bl, ba + PBSZ);
            MMA_BF16(c[t], ah[0], bh[0], bh[1]);
            MMA_BF16(c[t], al[0], bh[0], bh[1]);
            MMA_BF16(c[t], ah[0], bl[0], bl[1]);
            MMA_BF16(c[t], ah[1], bh[2], bh[3]);
            MMA_BF16(c[t], al[1], bh[2], bh[3]);
            MMA_BF16(c[t], ah[1], bl[2], bl[3]);
        }
    }

    uint32_t* hip[3] = { (uint32_t*)g_kh, (uint32_t*)g_qh, (uint32_t*)g_vh };
    uint32_t* lop[2] = { (uint32_t*)g_kl, (uint32_t*)g_ql };
    const int r1 = row0 + 16 * rg + (lane >> 2);
#pragma unroll
    for (int t = 0; t < 6; t++) {
        int g = cg * 6 + t;
        int mat = g >> 3, cu = (g & 7) * 4 + (lane & 3);
        if (mat == 2) {   // V: single fp16
            hip[2][(size_t)r1 * 32 + cu] = pack_h2(c[t][0], c[t][1]);
            hip[2][(size_t)(r1 + 8) * 32 + cu] = pack_h2(c[t][2], c[t][3]);
        } else {
            uint32_t h0, l0, h1, l1;
            split2pack(c[t][0], c[t][1], h0, l0);
            split2pack(c[t][2], c[t][3], h1, l1);
            hip[mat][(size_t)r1 * 32 + cu] = h0;
            lop[mat][(size_t)r1 * 32 + cu] = l0;
            hip[mat][(size_t)(r1 + 8) * 32 + cu] = h1;
            lop[mat][(size_t)(r1 + 8) * 32 + cu] = l1;
        }
    }
}

// ========== Kernel 2: mma.sync flash attention (per-tile hoisted max) ==========
#define ROWB 144
#define MATB 9216
#define BUFB 27648

__device__ __forceinline__ void load_tile(uint32_t sb, int buf, int grow0, int tid) {
    const char* srcs[3] = { (const char*)g_qh, (const char*)g_ql, (const char*)g_vh };
#pragma unroll
    for (int i = 0; i < 6; i++) {
        int idx = tid + i * 256;
        int mat = idx >> 9;
        int r = (idx >> 3) & 63, c8 = idx & 7;
        const char* g = srcs[mat] + ((size_t)(grow0 + r) * 64 + c8 * 8) * 2;
        uint32_t d = sb + buf * BUFB + mat * MATB + r * ROWB + c8 * 16;
        CP_ASYNC16(d, g);
    }
}

__global__ __launch_bounds__(256, 1) void attn_kernel()
{
    extern __shared__ __align__(16) char smem[];
    const uint32_t sb = smem_to_u32(smem);
    const int tid = threadIdx.x;
    const int wid = tid >> 5, lane = tid & 31;
    const int split = blockIdx.x >> 6;
    const int b = (blockIdx.x >> 5) & 1;
    const int n0 = (blockIdx.x & 31) * 128;
    const int kv0 = b * NPOS + split * 1024;
    const int r0 = wid << 4;

#pragma unroll
    for (int i = 0; i < 8; i++) {
        int idx = tid + i * 256;
        int m = idx >> 10;
        int r = (idx >> 3) & 127, c8 = idx & 7;
        const __nv_bfloat16* src = m ? g_kl : g_kh;
        const char* g = (const char*)(src + (size_t)(b * NPOS + n0 + r) * 64 + c8 * 8);
        CP_ASYNC16(sb + m * 18432 + r * ROWB + c8 * 16, g);
    }
    CP_COMMIT(); CP_WAIT(0);
    __syncthreads();

    uint32_t qh[4][4], ql[4][4];
#pragma unroll
    for (int kt = 0; kt < 4; kt++) {
        uint32_t a = sb + (r0 + (lane & 15)) * ROWB + (16 * kt + ((lane >> 4) << 3)) * 2;
        LDSM_X4(qh[kt], a);
        LDSM_X4(ql[kt], a + 18432);
    }
    __syncthreads();

    float o[8][4];
#pragma unroll
    for (int i = 0; i < 8; i++)
#pragma unroll
        for (int j = 0; j < 4; j++) o[i][j] = 0.f;
    float l0 = 0.f, l1 = 0.f, m0 = -1e30f, m1 = -1e30f;

    load_tile(sb, 0, kv0, tid);
    CP_COMMIT();

    for (int t = 0; t < 16; t++) {
        __syncthreads();
        if (t + 1 < 16) {
            load_tile(sb, (t + 1) & 1, kv0 + (t + 1) * 64, tid);
            CP_COMMIT(); CP_WAIT(1);
        } else CP_WAIT(0);
        __syncthreads();

        const uint32_t base = sb + (t & 1) * BUFB;

        float cs[4][8];
#pragma unroll
        for (int j = 0; j < 4; j++) {
#pragma unroll
            for (int e = 0; e < 8; e++) cs[j][e] = 0.f;
            uint32_t arow0 = base + (16 * j + (lane & 7)) * ROWB + ((lane >> 3) & 3) * 16;
            uint32_t arow1 = arow0 + 8 * ROWB;
#pragma unroll
            for (int kp = 0; kp < 2; kp++) {
                uint32_t bh[4], bl[4];
                LDSM_X4(bh, arow0 + kp * 64);
                LDSM_X4(bl, arow0 + kp * 64 + MATB);
                MMA_BF16(&cs[j][0], qh[2 * kp], bh[0], bh[1]);
                MMA_BF16(&cs[j][0], ql[2 * kp], bh[0], bh[1]);
                MMA_BF16(&cs[j][0], qh[2 * kp], bl[0], bl[1]);
                MMA_BF16(&cs[j][0], qh[2 * kp + 1], bh[2], bh[3]);
                MMA_BF16(&cs[j][0], ql[2 * kp + 1], bh[2], bh[3]);
                MMA_BF16(&cs[j][0], qh[2 * kp + 1], bl[2], bl[3]);
                LDSM_X4(bh, arow1 + kp * 64);
                LDSM_X4(bl, arow1 + kp * 64 + MATB);
                MMA_BF16(&cs[j][4], qh[2 * kp], bh[0], bh[1]);
                MMA_BF16(&cs[j][4], ql[2 * kp], bh[0], bh[1]);
                MMA_BF16(&cs[j][4], qh[2 * kp], bl[0], bl[1]);
                MMA_BF16(&cs[j][4], qh[2 * kp + 1], bh[2], bh[3]);
                MMA_BF16(&cs[j][4], ql[2 * kp + 1], bh[2], bh[3]);
                MMA_BF16(&cs[j][4], qh[2 * kp + 1], bl[2], bl[3]);
            }
        }

        float jm0 = -1e30f, jm1 = -1e30f;
#pragma unroll
        for (int j = 0; j < 4; j++) {
            jm0 = fmaxf(jm0, fmaxf(fmaxf(cs[j][0], cs[j][1]), fmaxf(cs[j][4], cs[j][5])));
            jm1 = fmaxf(jm1, fmaxf(fmaxf(cs[j][2], cs[j][3]), fmaxf(cs[j][6], cs[j][7])));
        }
        jm0 = fmaxf(jm0, __shfl_xor_sync(0xffffffffu, jm0, 1));
        jm0 = fmaxf(jm0, __shfl_xor_sync(0xffffffffu, jm0, 2));
        jm1 = fmaxf(jm1, __shfl_xor_sync(0xffffffffu, jm1, 1));
        jm1 = fmaxf(jm1, __shfl_xor_sync(0xffffffffu, jm1, 2));
        float m0n = fmaxf(m0, jm0), m1n = fmaxf(m1, jm1);
        float s0 = __expf(m0 - m0n), s1 = __expf(m1 - m1n);
        m0 = m0n; m1 = m1n;
        l0 *= s0; l1 *= s1;
#pragma unroll
        for (int dt = 0; dt < 8; dt++) {
            o[dt][0] *= s0; o[dt][1] *= s0;
            o[dt][2] *= s1; o[dt][3] *= s1;
        }

#pragma unroll
        for (int j = 0; j < 4; j++) {
            float p00 = __expf(cs[j][0] - m0), p01 = __expf(cs[j][1] - m0);
            float p02 = __expf(cs[j][2] - m1), p03 = __expf(cs[j][3] - m1);
            float p10 = __expf(cs[j][4] - m0), p11 = __expf(cs[j][5] - m0);
            float p12 = __expf(cs[j][6] - m1), p13 = __expf(cs[j][7] - m1);
            l0 += (p00 + p01) + (p10 + p11);
            l1 += (p02 + p03) + (p12 + p13);
            uint32_t ph[4];
            ph[0] = pack_h2(p00, p01);
            ph[1] = pack_h2(p02, p03);
            ph[2] = pack_h2(p10, p11);
            ph[3] = pack_h2(p12, p13);
#pragma unroll
            for (int dp = 0; dp < 4; dp++) {
                uint32_t av = base + 2 * MATB + (16 * j + (lane & 15)) * ROWB
                              + dp * 32 + ((lane >> 4) & 1) * 16;
                uint32_t vh[4];
                LDSM_X4T(vh, av);
                MMA_FP16(o[2 * dp], ph, vh[0], vh[1]);
                MMA_FP16(o[2 * dp + 1], ph, vh[2], vh[3]);
            }
        }
    }

    l0 += __shfl_xor_sync(0xffffffffu, l0, 1);
    l0 += __shfl_xor_sync(0xffffffffu, l0, 2);
    l1 += __shfl_xor_sync(0xffffffffu, l1, 1);
    l1 += __shfl_xor_sync(0xffffffffu, l1, 2);

    const int rg = b * NPOS + n0 + r0 + (lane >> 2);
    float* dst = g_opart + (size_t)split * NROWS * 64;
#pragma unroll
    for (int dt = 0; dt < 8; dt++) {
        ((float2*)(dst + (size_t)rg * 64 + dt * 8))[lane & 3] =
            make_float2(o[dt][0], o[dt][1]);
        ((float2*)(dst + (size_t)(rg + 8) * 64 + dt * 8))[lane & 3] =
            make_float2(o[dt][2], o[dt][3]);
    }
    if ((lane & 3) == 0) {
        g_lpart[split * NROWS + rg] = l0;
        g_lpart[split * NROWS + rg + 8] = l1;
        g_mpart[split * NROWS + rg] = m0;
        g_mpart[split * NROWS + rg + 8] = m1;
    }
}

// ====== Kernel 3: merge 4 splits + outproj (single-term fp16) + BN ======
// Grid 256 x 32 rows; 8 warps = 2 rowgrp(m16) x 4 colgrp(64 cols); 2 CTAs/SM.
// SMEM: A fp16 32x144 = 4608; B fp16 256x144 = 36864.
#define OAH 4608
#define OBH 36864

__global__ __launch_bounds__(256, 2) void outproj_mma(
    const float* __restrict__ gamma, const float* __restrict__ beta,
    float* __restrict__ out)
{
    extern __shared__ __align__(16) char smem[];
    const uint32_t sb = smem_to_u32(smem);
    const int tid = threadIdx.x;
    const int wid = tid >> 5, lane = tid & 31;
    const int rg = wid & 1, cg = wid >> 1;
    const int row0 = blockIdx.x * 32;

    // stage B: Wo^T fp16, 2048 16B-chunks
#pragma unroll
    for (int i = 0; i < 8; i++) {
        int idx = tid + i * 256;
        int r = idx >> 3, c = idx & 7;
        CP_ASYNC16(sb + OAH + r * ROWB + c * 16, (const char*)(g_woh + r * 64 + c * 8));
    }
    CP_COMMIT();

    // stage A: merge 4 split-KV partials (log-sum-exp), convert fp16
    {
        int r = tid >> 3, cq = tid & 7;
        int rgr = row0 + r;
        float ms[4], w[4];
        float M = -1e30f;
#pragma unroll
        for (int s = 0; s < 4; s++) {
            ms[s] = g_mpart[s * NROWS + rgr];
            M = fmaxf(M, ms[s]);
        }
        float denom = 0.f;
#pragma unroll
        for (int s = 0; s < 4; s++) {
            w[s] = __expf(ms[s] - M);
            denom += w[s] * g_lpart[s * NROWS + rgr];
        }
        float inv = 1.f / denom;
        uint32_t hpk[4];
#pragma unroll
        for (int e = 0; e < 2; e++) {
            int c4 = cq * 2 + e;
            float4 u = make_float4(0.f, 0.f, 0.f, 0.f);
#pragma unroll
            for (int s = 0; s < 4; s++) {
                float4 p = ((const float4*)(g_opart + (size_t)s * NROWS * 64
                                            + (size_t)rgr * 64))[c4];
                u.x += w[s] * p.x; u.y += w[s] * p.y;
                u.z += w[s] * p.z; u.w += w[s] * p.w;
            }
            hpk[2 * e]     = pack_h2(u.x * inv, u.y * inv);
            hpk[2 * e + 1] = pack_h2(u.z * inv, u.w * inv);
        }
        *(uint4*)(smem + r * ROWB + cq * 16) =
            make_uint4(hpk[0], hpk[1], hpk[2], hpk[3]);
    }
    CP_WAIT(0);
    __syncthreads();

    uint32_t ah[4][4];
#pragma unroll
    for (int kt = 0; kt < 4; kt++) {
        uint32_t a = sb + (16 * rg + (lane & 15)) * ROWB + kt * 32 + ((lane >> 4) << 4);
        LDSM_X4(ah[kt], a);
    }

    float acc[8][4];
#pragma unroll
    for (int t = 0; t < 8; t++)
#pragma unroll
        for (int j = 0; j < 4; j++) acc[t][j] = 0.f;

#pragma unroll
    for (int t = 0; t < 8; t++) {
        int nrow0 = cg * 64 + t * 8;
#pragma unroll
        for (int kp = 0; kp < 2; kp++) {
            uint32_t bh[4];
            uint32_t ba = sb + OAH + (nrow0 + (lane & 7)) * ROWB
                          + kp * 64 + ((lane >> 3) & 3) * 16;
            LDSM_X4(bh, ba);
            MMA_FP16(acc[t], ah[2 * kp], bh[0], bh[1]);
            MMA_FP16(acc[t], ah[2 * kp + 1], bh[2], bh[3]);
        }
    }

    const float sc = rsqrtf(1.0f + 1e-3f);
    const int r1 = row0 + 16 * rg + (lane >> 2);
#pragma unroll
    for (int t = 0; t < 8; t++) {
        int col = cg * 64 + t * 8 + (lane & 3) * 2;
        float g0 = __ldg(gamma + col) * sc, g1 = __ldg(gamma + col + 1) * sc;
        float b0 = __ldg(beta + col), b1 = __ldg(beta + col + 1);
        *(float2*)(out + (size_t)r1 * 256 + col) =
            make_float2(fmaf(acc[t][0], g0, b0), fmaf(acc[t][1], g1, b1));
        *(float2*)(out + (size_t)(r1 + 8) * 256 + col) =
            make_float2(fmaf(acc[t][2], g0, b0), fmaf(acc[t][3], g1, b1));
    }
}

extern "C" void kernel_launch(void* const* d_in, const int* in_sizes, int n_in,
                              void* d_out, int out_size) {
    const float* x     = (const float*)d_in[0];
    const float* Wk    = (const float*)d_in[1];
    const float* Wq    = (const float*)d_in[2];
    const float* Wv    = (const float*)d_in[3];
    const float* Wo    = (const float*)d_in[4];
    const float* gamma = (const float*)d_in[5];
    const float* beta  = (const float*)d_in[6];
    float* out = (float*)d_out;

    cudaFuncSetAttribute(proj_mma, cudaFuncAttributeMaxDynamicSharedMemorySize, 2 * PBUF);
    cudaFuncSetAttribute(attn_kernel, cudaFuncAttributeMaxDynamicSharedMemorySize, 2 * BUFB);
    cudaFuncSetAttribute(outproj_mma, cudaFuncAttributeMaxDynamicSharedMemorySize,
                         OAH + OBH);

    split_w_kernel<<<256, 256>>>(Wk, Wq, Wv, Wo);
    proj_mma<<<256, 256, 2 * PBUF>>>(x);
    attn_kernel<<<256, 256, 2 * BUFB>>>();
    outproj_mma<<<256, 256, OAH + OBH>>>(gamma, beta, out);
}